// round 2
// baseline (speedup 1.0000x reference)
#include <cuda_runtime.h>
#include <math.h>

// ---------------------------------------------------------------------------
// Contrast: proj(MLP) -> shared QKV -> dual cross-attention, fp32 in/out.
// All GEMMs run as NT (A[M,K] row-major, B[N,K] row-major) on tf32 mma.sync.
// SPLIT=1 GEMMs use 3xTF32 (hi/lo split) for ~fp32 accuracy.
// ---------------------------------------------------------------------------

namespace {
constexpr int BM = 128, BN = 128, BK = 32;
constexpr int KBLK = 1032;   // words per k-octet slab: 128 rows * 8 + 8 pad
}

// ------------------------------ scratch ------------------------------------
__device__ float g_H  [16384 * 1024];
__device__ float g_Pm [16384 * 512];
__device__ float g_Qm [16384 * 512];
__device__ float g_Km [16384 * 512];
__device__ float g_Vm [16384 * 512];
__device__ float g_VT [16384 * 512];
__device__ float g_W1T[1024 * 1024];
__device__ float g_W2T[512 * 1024];
__device__ float g_WqT[512 * 512];
__device__ float g_WkT[512 * 512];
__device__ float g_WvT[512 * 512];
__device__ float g_S  [67108864];

// ------------------------------ helpers ------------------------------------
__device__ __forceinline__ unsigned f2tf(float x) {
    unsigned u; asm("cvt.rna.tf32.f32 %0, %1;" : "=r"(u) : "f"(x)); return u;
}

__device__ __forceinline__ void mma_tf32(float* c,
                                         unsigned a0, unsigned a1, unsigned a2, unsigned a3,
                                         unsigned b0, unsigned b1) {
    asm volatile(
        "mma.sync.aligned.m16n8k8.row.col.f32.tf32.tf32.f32 "
        "{%0,%1,%2,%3}, {%4,%5,%6,%7}, {%8,%9}, {%0,%1,%2,%3};"
        : "+f"(c[0]), "+f"(c[1]), "+f"(c[2]), "+f"(c[3])
        : "r"(a0), "r"(a1), "r"(a2), "r"(a3), "r"(b0), "r"(b1));
}

// ------------------------------ transpose ----------------------------------
__global__ void __launch_bounds__(256, 4)
transpose_k(const float* __restrict__ src, float* __restrict__ dst, int R, int C)
{
    __shared__ float t[32][33];
    const int bx = blockIdx.x * 32;
    const int by = blockIdx.y * 32;
    const int x  = bx + threadIdx.x;
    #pragma unroll
    for (int i = threadIdx.y; i < 32; i += 8)
        t[i][threadIdx.x] = src[(size_t)(by + i) * C + x];
    __syncthreads();
    const int xo = by + threadIdx.x;
    #pragma unroll
    for (int i = threadIdx.y; i < 32; i += 8)
        dst[(size_t)(bx + i) * R + xo] = t[threadIdx.x][i];
}

// ------------------------------ GEMM (NT) ----------------------------------
// C[M,N] = epi(A[M,K] @ B[N,K]^T)
// EPI 0: v *= scale ; EPI 1: v += bias[col] ; EPI 2: elu(v + bias[col])
// SPLIT=1: 3xTF32 (hi*hi + hi*lo + lo*hi)
template <int EPI, int SPLIT>
__global__ void __launch_bounds__(256, 1)
gemm_nt(const float* __restrict__ A, const float* __restrict__ B,
        const float* __restrict__ bias, float* __restrict__ C,
        int M, int N, int K, int ldc, int coff, float scale)
{
    extern __shared__ unsigned smem_u[];
    constexpr int SLAB = 4 * KBLK;
    unsigned* Xs = smem_u;                           // A hi
    unsigned* Xl = Xs + SLAB;                        // A lo (split only)
    unsigned* Ys = smem_u + (SPLIT ? 2 : 1) * SLAB;  // B hi
    unsigned* Yl = Ys + SLAB;                        // B lo (split only)

    const int tid  = threadIdx.x;
    const int bm   = blockIdx.y * BM;
    const int bn   = blockIdx.x * BN;
    const int warp = tid >> 5;
    const int lane = tid & 31;
    const int wm   = (warp >> 2) * 64;
    const int wn   = (warp & 3) * 32;
    const int g    = lane >> 2;              // 0..7
    const int tk   = lane & 3;               // k base
    const int t2   = tk * 2;                 // C col offset
    const int swz  = ((g >> 2) & 1) * 4;     // read swizzle (row bit2 == g bit2)
    const int ks   = tk ^ swz;               // physical k slot for a0/b0

    // staging
    const int srow = tid >> 3;               // 0..31 (+32*i)
    const int scol = (tid & 7) * 4;          // 0..28
    const int sswz = ((srow >> 2) & 1) * 4;
    const unsigned sidx = (unsigned)((scol >> 3) * KBLK + srow * 8 + ((scol & 7) ^ sswz));

    float acc[4][4][4];
    #pragma unroll
    for (int i = 0; i < 4; i++)
        #pragma unroll
        for (int j = 0; j < 4; j++)
            #pragma unroll
            for (int e = 0; e < 4; e++) acc[i][j][e] = 0.f;

    float4 ra[4], rb[4];
    const int ktiles = K / BK;

    auto gload = [&](int kt) {
        const int k0 = kt * BK + scol;
        #pragma unroll
        for (int i = 0; i < 4; i++)
            ra[i] = *reinterpret_cast<const float4*>(A + (size_t)(bm + srow + 32 * i) * K + k0);
        #pragma unroll
        for (int i = 0; i < 4; i++)
            rb[i] = *reinterpret_cast<const float4*>(B + (size_t)(bn + srow + 32 * i) * K + k0);
    };

    auto cvt1 = [&](float x, unsigned& hi, unsigned& lo) {
        hi = f2tf(x);
        if (SPLIT) lo = f2tf(x - __uint_as_float(hi));
    };

    auto sstore = [&]() {
        #pragma unroll
        for (int i = 0; i < 4; i++) {
            uint4 h, l;
            cvt1(ra[i].x, h.x, l.x); cvt1(ra[i].y, h.y, l.y);
            cvt1(ra[i].z, h.z, l.z); cvt1(ra[i].w, h.w, l.w);
            *reinterpret_cast<uint4*>(&Xs[sidx + i * 256]) = h;
            if (SPLIT) *reinterpret_cast<uint4*>(&Xl[sidx + i * 256]) = l;
        }
        #pragma unroll
        for (int i = 0; i < 4; i++) {
            uint4 h, l;
            cvt1(rb[i].x, h.x, l.x); cvt1(rb[i].y, h.y, l.y);
            cvt1(rb[i].z, h.z, l.z); cvt1(rb[i].w, h.w, l.w);
            *reinterpret_cast<uint4*>(&Ys[sidx + i * 256]) = h;
            if (SPLIT) *reinterpret_cast<uint4*>(&Yl[sidx + i * 256]) = l;
        }
    };

    auto compute = [&]() {
        #pragma unroll
        for (int ksi = 0; ksi < 4; ksi++) {
            const unsigned base = (unsigned)(ksi * KBLK);
            unsigned a[4][4], b[4][2];
            #pragma unroll
            for (int mf = 0; mf < 4; mf++) {
                const unsigned p = base + (unsigned)((wm + mf * 16 + g) * 8 + ks);
                a[mf][0] = Xs[p];       a[mf][1] = Xs[p + 64];
                a[mf][2] = Xs[p ^ 4];   a[mf][3] = Xs[(p + 64) ^ 4];
            }
            #pragma unroll
            for (int nf = 0; nf < 4; nf++) {
                const unsigned q = base + (unsigned)((wn + nf * 8 + g) * 8 + ks);
                b[nf][0] = Ys[q];       b[nf][1] = Ys[q ^ 4];
            }
            #pragma unroll
            for (int mf = 0; mf < 4; mf++)
                #pragma unroll
                for (int nf = 0; nf < 4; nf++)
                    mma_tf32(acc[mf][nf], a[mf][0], a[mf][1], a[mf][2], a[mf][3],
                             b[nf][0], b[nf][1]);
            if (SPLIT) {
                unsigned bl[4][2];
                #pragma unroll
                for (int nf = 0; nf < 4; nf++) {
                    const unsigned q = base + (unsigned)((wn + nf * 8 + g) * 8 + ks);
                    bl[nf][0] = Yl[q];  bl[nf][1] = Yl[q ^ 4];
                }
                #pragma unroll
                for (int mf = 0; mf < 4; mf++)
                    #pragma unroll
                    for (int nf = 0; nf < 4; nf++)
                        mma_tf32(acc[mf][nf], a[mf][0], a[mf][1], a[mf][2], a[mf][3],
                                 bl[nf][0], bl[nf][1]);
                unsigned al[4][4];
                #pragma unroll
                for (int mf = 0; mf < 4; mf++) {
                    const unsigned p = base + (unsigned)((wm + mf * 16 + g) * 8 + ks);
                    al[mf][0] = Xl[p];      al[mf][1] = Xl[p + 64];
                    al[mf][2] = Xl[p ^ 4];  al[mf][3] = Xl[(p + 64) ^ 4];
                }
                #pragma unroll
                for (int mf = 0; mf < 4; mf++)
                    #pragma unroll
                    for (int nf = 0; nf < 4; nf++)
                        mma_tf32(acc[mf][nf], al[mf][0], al[mf][1], al[mf][2], al[mf][3],
                                 b[nf][0], b[nf][1]);
            }
        }
    };

    gload(0);
    sstore();
    __syncthreads();
    for (int kt = 0; kt < ktiles; kt++) {
        if (kt + 1 < ktiles) gload(kt + 1);
        compute();
        __syncthreads();
        if (kt + 1 < ktiles) { sstore(); __syncthreads(); }
    }

    // epilogue
    #pragma unroll
    for (int mf = 0; mf < 4; mf++) {
        #pragma unroll
        for (int nf = 0; nf < 4; nf++) {
            const int row = bm + wm + mf * 16 + g;
            const int col = bn + wn + nf * 8 + t2;
            float v0 = acc[mf][nf][0], v1 = acc[mf][nf][1];
            float v2 = acc[mf][nf][2], v3 = acc[mf][nf][3];
            if (EPI == 0) {
                v0 *= scale; v1 *= scale; v2 *= scale; v3 *= scale;
            } else {
                const float bb0 = bias[col], bb1 = bias[col + 1];
                v0 += bb0; v1 += bb1; v2 += bb0; v3 += bb1;
                if (EPI == 2) {
                    v0 = v0 > 0.f ? v0 : expm1f(v0);
                    v1 = v1 > 0.f ? v1 : expm1f(v1);
                    v2 = v2 > 0.f ? v2 : expm1f(v2);
                    v3 = v3 > 0.f ? v3 : expm1f(v3);
                }
            }
            *reinterpret_cast<float2*>(C + (size_t)row * ldc + coff + col)       = make_float2(v0, v1);
            *reinterpret_cast<float2*>(C + (size_t)(row + 8) * ldc + coff + col) = make_float2(v2, v3);
        }
    }
}

// ------------------------------ softmax ------------------------------------
__global__ void __launch_bounds__(256, 1)
softmax_rows(float* __restrict__ S)
{
    const int row = blockIdx.x;
    float4* p = reinterpret_cast<float4*>(S + (size_t)row * 8192);
    const int tid = threadIdx.x;

    float4 v[8];
    #pragma unroll
    for (int i = 0; i < 8; i++) v[i] = p[tid + 256 * i];

    float m = -3.402823e38f;
    #pragma unroll
    for (int i = 0; i < 8; i++)
        m = fmaxf(m, fmaxf(fmaxf(v[i].x, v[i].y), fmaxf(v[i].z, v[i].w)));

    __shared__ float red[8];
    #pragma unroll
    for (int o = 16; o; o >>= 1) m = fmaxf(m, __shfl_xor_sync(0xffffffffu, m, o));
    if ((tid & 31) == 0) red[tid >> 5] = m;
    __syncthreads();
    float mm = red[0];
    #pragma unroll
    for (int i = 1; i < 8; i++) mm = fmaxf(mm, red[i]);

    float s = 0.f;
    #pragma unroll
    for (int i = 0; i < 8; i++) {
        v[i].x = __expf(v[i].x - mm); s += v[i].x;
        v[i].y = __expf(v[i].y - mm); s += v[i].y;
        v[i].z = __expf(v[i].z - mm); s += v[i].z;
        v[i].w = __expf(v[i].w - mm); s += v[i].w;
    }
    #pragma unroll
    for (int o = 16; o; o >>= 1) s += __shfl_xor_sync(0xffffffffu, s, o);
    __syncthreads();
    if ((tid & 31) == 0) red[tid >> 5] = s;
    __syncthreads();
    float st = 0.f;
    #pragma unroll
    for (int i = 0; i < 8; i++) st += red[i];
    const float inv = 1.0f / st;

    #pragma unroll
    for (int i = 0; i < 8; i++) {
        v[i].x *= inv; v[i].y *= inv; v[i].z *= inv; v[i].w *= inv;
        p[tid + 256 * i] = v[i];
    }
}

// ------------------------------ launcher -----------------------------------
extern "C" void kernel_launch(void* const* d_in, const int* in_sizes, int n_in,
                              void* d_out, int out_size)
{
    const float* za = (const float*)d_in[0];
    const float* zb = (const float*)d_in[1];
    const float* W1 = (const float*)d_in[2];
    const float* b1 = (const float*)d_in[3];
    const float* W2 = (const float*)d_in[4];
    const float* b2 = (const float*)d_in[5];
    const float* Wq = (const float*)d_in[6];
    const float* bq = (const float*)d_in[7];
    const float* Wk = (const float*)d_in[8];
    const float* bk = (const float*)d_in[9];
    const float* Wv = (const float*)d_in[10];
    const float* bv = (const float*)d_in[11];
    float* out = (float*)d_out;

    float *H, *P, *Q, *Kp, *V, *VT, *W1T, *W2T, *WqT, *WkT, *WvT, *S;
    cudaGetSymbolAddress((void**)&H,   g_H);
    cudaGetSymbolAddress((void**)&P,   g_Pm);
    cudaGetSymbolAddress((void**)&Q,   g_Qm);
    cudaGetSymbolAddress((void**)&Kp,  g_Km);
    cudaGetSymbolAddress((void**)&V,   g_Vm);
    cudaGetSymbolAddress((void**)&VT,  g_VT);
    cudaGetSymbolAddress((void**)&W1T, g_W1T);
    cudaGetSymbolAddress((void**)&W2T, g_W2T);
    cudaGetSymbolAddress((void**)&WqT, g_WqT);
    cudaGetSymbolAddress((void**)&WkT, g_WkT);
    cudaGetSymbolAddress((void**)&WvT, g_WvT);
    cudaGetSymbolAddress((void**)&S,   g_S);

    constexpr int SLAB_B = 4 * KBLK * 4;          // bytes per slab
    const int smem_single = 2 * SLAB_B;           // 33 KB
    const int smem_split  = 4 * SLAB_B;           // 66 KB
    cudaFuncSetAttribute(gemm_nt<0,0>, cudaFuncAttributeMaxDynamicSharedMemorySize, smem_single);
    cudaFuncSetAttribute(gemm_nt<1,0>, cudaFuncAttributeMaxDynamicSharedMemorySize, smem_single);
    cudaFuncSetAttribute(gemm_nt<0,1>, cudaFuncAttributeMaxDynamicSharedMemorySize, smem_split);
    cudaFuncSetAttribute(gemm_nt<1,1>, cudaFuncAttributeMaxDynamicSharedMemorySize, smem_split);
    cudaFuncSetAttribute(gemm_nt<2,1>, cudaFuncAttributeMaxDynamicSharedMemorySize, smem_split);

    const dim3 blk(256);
    const dim3 tblk(32, 8);
    const float inv_scale = 1.0f / 16.0f;   // 1/sqrt(OUT/2)
    const size_t HALF = (size_t)8192 * 512;

    transpose_k<<<dim3(32, 32), tblk>>>(W1, W1T, 1024, 1024);
    transpose_k<<<dim3(16, 32), tblk>>>(W2, W2T, 1024, 512);
    transpose_k<<<dim3(16, 16), tblk>>>(Wq, WqT, 512, 512);
    transpose_k<<<dim3(16, 16), tblk>>>(Wk, WkT, 512, 512);
    transpose_k<<<dim3(16, 16), tblk>>>(Wv, WvT, 512, 512);

    // proj layer 1 (split): H = ELU(X @ W1 + b1)
    gemm_nt<2,1><<<dim3(8, 64), blk, smem_split>>>(za, W1T, b1, H,                     8192, 1024, 1024, 1024, 0, 1.f);
    gemm_nt<2,1><<<dim3(8, 64), blk, smem_split>>>(zb, W1T, b1, H + (size_t)8192*1024, 8192, 1024, 1024, 1024, 0, 1.f);
    // proj layer 2 (split): P = H @ W2 + b2
    gemm_nt<1,1><<<dim3(4, 128), blk, smem_split>>>(H, W2T, b2, P, 16384, 512, 1024, 512, 0, 1.f);
    // QKV (Q,K split; V single)
    gemm_nt<1,1><<<dim3(4, 128), blk, smem_split>>>(P, WqT, bq, Q,  16384, 512, 512, 512, 0, 1.f);
    gemm_nt<1,1><<<dim3(4, 128), blk, smem_split>>>(P, WkT, bk, Kp, 16384, 512, 512, 512, 0, 1.f);
    gemm_nt<1,0><<<dim3(4, 128), blk, smem_single>>>(P, WvT, bv, V, 16384, 512, 512, 512, 0, 1.f);
    // V transposed per half -> [512, 8192]
    transpose_k<<<dim3(16, 256), tblk>>>(V,        VT,        8192, 512);
    transpose_k<<<dim3(16, 256), tblk>>>(V + HALF, VT + HALF, 8192, 512);

    // direction A
    gemm_nt<0,1><<<dim3(64, 64), blk, smem_split>>>(Q, Kp + HALF, nullptr, S, 8192, 8192, 512, 8192, 0, inv_scale);
    softmax_rows<<<8192, blk>>>(S);
    gemm_nt<0,0><<<dim3(4, 64), blk, smem_single>>>(S, VT + HALF, nullptr, out, 8192, 512, 8192, 1024, 0, 1.f);

    // direction B
    gemm_nt<0,1><<<dim3(64, 64), blk, smem_split>>>(Q + HALF, Kp, nullptr, S, 8192, 8192, 512, 8192, 0, inv_scale);
    softmax_rows<<<8192, blk>>>(S);
    gemm_nt<0,0><<<dim3(4, 64), blk, smem_single>>>(S, VT, nullptr, out, 8192, 512, 8192, 1024, 512, 1.f);
}

// round 4
// speedup vs baseline: 1.3974x; 1.3974x over previous
#include <cuda_runtime.h>
#include <cuda_bf16.h>
#include <cuda_fp16.h>
#include <math.h>

// ---------------------------------------------------------------------------
// Contrast on legacy mma.sync (baseline PTX only; harness targets sm_103 non-a).
// All GEMMs NT: C = A[M,K] @ B[N,K]^T.
//  PREC 0: bf16 3-way split (hi*hi + hi*lo + lo*hi), m16n8k16, fp32 accum.
//  PREC 1: fp16 single (A pre-packed fp16, B f32->fp16), m16n8k16, fp32 accum.
// CTA tile 128x128, BK=64, 8 warps (64x32 warp tiles).
// ---------------------------------------------------------------------------

namespace {
constexpr int KBLK = 1032;        // u32 words per k16-block slab: 128*8 + 8 pad
constexpr int SLAB = 4 * KBLK;    // 4 k16-blocks per BK=64 tile
}

// ------------------------------ scratch ------------------------------------
__device__ float    g_H  [16384 * 1024];
__device__ float    g_Pm [16384 * 512];
__device__ float    g_Qm [16384 * 512];
__device__ float    g_Km [16384 * 512];
__device__ float    g_Vm [16384 * 512];
__device__ float    g_VT [16384 * 512];
__device__ float    g_W1T[1024 * 1024];
__device__ float    g_W2T[512 * 1024];
__device__ float    g_WqT[512 * 512];
__device__ float    g_WkT[512 * 512];
__device__ float    g_WvT[512 * 512];
__device__ float    g_S  [67108864];     // fp32 scores 8192x8192
__device__ unsigned g_Sh [33554432];     // fp16 softmaxed scores (half2-packed)

// ------------------------------ helpers ------------------------------------
__device__ __forceinline__ void mma_bf16(float* c, const unsigned* a, const unsigned* b) {
    asm volatile(
        "mma.sync.aligned.m16n8k16.row.col.f32.bf16.bf16.f32 "
        "{%0,%1,%2,%3}, {%4,%5,%6,%7}, {%8,%9}, {%0,%1,%2,%3};"
        : "+f"(c[0]), "+f"(c[1]), "+f"(c[2]), "+f"(c[3])
        : "r"(a[0]), "r"(a[1]), "r"(a[2]), "r"(a[3]), "r"(b[0]), "r"(b[1]));
}

__device__ __forceinline__ void mma_fp16(float* c, const unsigned* a, const unsigned* b) {
    asm volatile(
        "mma.sync.aligned.m16n8k16.row.col.f32.f16.f16.f32 "
        "{%0,%1,%2,%3}, {%4,%5,%6,%7}, {%8,%9}, {%0,%1,%2,%3};"
        : "+f"(c[0]), "+f"(c[1]), "+f"(c[2]), "+f"(c[3])
        : "r"(a[0]), "r"(a[1]), "r"(a[2]), "r"(a[3]), "r"(b[0]), "r"(b[1]));
}

// pack two floats as bf16x2 hi + residual lo
__device__ __forceinline__ void split2(float x, float y, unsigned& hi, unsigned& lo) {
    __nv_bfloat16 hx = __float2bfloat16(x);
    __nv_bfloat16 hy = __float2bfloat16(y);
    __nv_bfloat16 lx = __float2bfloat16(x - __bfloat162float(hx));
    __nv_bfloat16 ly = __float2bfloat16(y - __bfloat162float(hy));
    hi = ((unsigned)__bfloat16_as_ushort(hy) << 16) | (unsigned)__bfloat16_as_ushort(hx);
    lo = ((unsigned)__bfloat16_as_ushort(ly) << 16) | (unsigned)__bfloat16_as_ushort(lx);
}

__device__ __forceinline__ unsigned packh2(float x, float y) {
    __half2 h = __floats2half2_rn(x, y);
    return *reinterpret_cast<unsigned*>(&h);
}

// ------------------------------ transpose ----------------------------------
__global__ void __launch_bounds__(256, 4)
transpose_k(const float* __restrict__ src, float* __restrict__ dst, int R, int C)
{
    __shared__ float t[32][33];
    const int bx = blockIdx.x * 32;
    const int by = blockIdx.y * 32;
    const int x  = bx + threadIdx.x;
    #pragma unroll
    for (int i = threadIdx.y; i < 32; i += 8)
        t[i][threadIdx.x] = src[(size_t)(by + i) * C + x];
    __syncthreads();
    const int xo = by + threadIdx.x;
    #pragma unroll
    for (int i = threadIdx.y; i < 32; i += 8)
        dst[(size_t)(bx + i) * R + xo] = t[threadIdx.x][i];
}

// ------------------------------ GEMM ---------------------------------------
// EPI 0: v *= scale ; EPI 1: v += bias[col] ; EPI 2: elu(v + bias[col])
// PREC 0: A,B f32 -> bf16 split3. PREC 1: A fp16-packed, B f32 -> fp16 single.
template <int EPI, int PREC>
__global__ void __launch_bounds__(256, 1)
gemm_mm(const void* __restrict__ Av, const float* __restrict__ B,
        const float* __restrict__ bias, float* __restrict__ C,
        int M, int N, int K, int ldc, int coff, float scale)
{
    extern __shared__ unsigned sm[];
    unsigned* Xh = sm;                               // A hi
    unsigned* Xl = Xh + SLAB;                        // A lo (split only)
    unsigned* Yh = sm + (PREC == 0 ? 2 : 1) * SLAB;  // B hi
    unsigned* Yl = Yh + SLAB;                        // B lo (split only)

    const int tid  = threadIdx.x;
    const int bm   = blockIdx.y * 128;
    const int bn   = blockIdx.x * 128;
    const int warp = tid >> 5;
    const int lane = tid & 31;
    const int wm   = (warp >> 2) * 64;
    const int wn   = (warp & 3) * 32;
    const int g    = lane >> 2;              // 0..7
    const int tk   = lane & 3;
    const int t2   = tk * 2;
    const int swz  = ((g >> 2) & 1) * 4;
    const int ks   = tk ^ swz;               // physical word slot

    // staging mapping
    const int srow  = tid >> 3;              // 0..31 (+32*i)
    const int scol8 = (tid & 7) * 8;         // k offset 0..56
    const int sblk  = scol8 >> 4;            // k16-block 0..3
    const int sw0   = ((scol8 & 15) >> 1) ^ (((srow >> 2) & 1) * 4);  // word 0 or 4, swizzled

    float acc[4][4][4];
    #pragma unroll
    for (int i = 0; i < 4; i++)
        #pragma unroll
        for (int j = 0; j < 4; j++)
            #pragma unroll
            for (int e = 0; e < 4; e++) acc[i][j][e] = 0.f;

    const float* Af = (const float*)Av;
    const unsigned* Ah = (const unsigned*)Av;   // fp16-packed view (pitch K/2 words)

    float4 ra[4][2], rb[4][2];
    uint4  qa[4];
    const int ktiles = K / 64;

    auto gload = [&](int kt) {
        const int k0 = kt * 64 + scol8;
        if (PREC == 0) {
            #pragma unroll
            for (int i = 0; i < 4; i++) {
                const float* p = Af + (size_t)(bm + srow + 32 * i) * K + k0;
                ra[i][0] = *reinterpret_cast<const float4*>(p);
                ra[i][1] = *reinterpret_cast<const float4*>(p + 4);
            }
        } else {
            #pragma unroll
            for (int i = 0; i < 4; i++)
                qa[i] = *reinterpret_cast<const uint4*>(
                    Ah + (size_t)(bm + srow + 32 * i) * (K >> 1) + (k0 >> 1));
        }
        #pragma unroll
        for (int i = 0; i < 4; i++) {
            const float* p = B + (size_t)(bn + srow + 32 * i) * K + k0;
            rb[i][0] = *reinterpret_cast<const float4*>(p);
            rb[i][1] = *reinterpret_cast<const float4*>(p + 4);
        }
    };

    auto sstore = [&]() {
        #pragma unroll
        for (int i = 0; i < 4; i++) {
            const unsigned sidx = (unsigned)(sblk * KBLK + (srow + 32 * i) * 8 + sw0);
            if (PREC == 0) {
                uint4 h, l;
                split2(ra[i][0].x, ra[i][0].y, h.x, l.x);
                split2(ra[i][0].z, ra[i][0].w, h.y, l.y);
                split2(ra[i][1].x, ra[i][1].y, h.z, l.z);
                split2(ra[i][1].z, ra[i][1].w, h.w, l.w);
                *reinterpret_cast<uint4*>(&Xh[sidx]) = h;
                *reinterpret_cast<uint4*>(&Xl[sidx]) = l;
            } else {
                *reinterpret_cast<uint4*>(&Xh[sidx]) = qa[i];
            }
            uint4 bh, bl;
            if (PREC == 0) {
                split2(rb[i][0].x, rb[i][0].y, bh.x, bl.x);
                split2(rb[i][0].z, rb[i][0].w, bh.y, bl.y);
                split2(rb[i][1].x, rb[i][1].y, bh.z, bl.z);
                split2(rb[i][1].z, rb[i][1].w, bh.w, bl.w);
                *reinterpret_cast<uint4*>(&Yh[sidx]) = bh;
                *reinterpret_cast<uint4*>(&Yl[sidx]) = bl;
            } else {
                bh.x = packh2(rb[i][0].x, rb[i][0].y);
                bh.y = packh2(rb[i][0].z, rb[i][0].w);
                bh.z = packh2(rb[i][1].x, rb[i][1].y);
                bh.w = packh2(rb[i][1].z, rb[i][1].w);
                *reinterpret_cast<uint4*>(&Yh[sidx]) = bh;
            }
        }
    };

    auto compute = [&]() {
        #pragma unroll
        for (int blk = 0; blk < 4; blk++) {
            const unsigned base = (unsigned)(blk * KBLK);
            unsigned a[4][4], b[4][2];
            #pragma unroll
            for (int mf = 0; mf < 4; mf++) {
                const unsigned p = base + (unsigned)((wm + mf * 16 + g) * 8 + ks);
                a[mf][0] = Xh[p];       a[mf][1] = Xh[p + 64];
                a[mf][2] = Xh[p ^ 4];   a[mf][3] = Xh[(p + 64) ^ 4];
            }
            #pragma unroll
            for (int nf = 0; nf < 4; nf++) {
                const unsigned q = base + (unsigned)((wn + nf * 8 + g) * 8 + ks);
                b[nf][0] = Yh[q];       b[nf][1] = Yh[q ^ 4];
            }
            #pragma unroll
            for (int mf = 0; mf < 4; mf++)
                #pragma unroll
                for (int nf = 0; nf < 4; nf++) {
                    if (PREC == 0) mma_bf16(acc[mf][nf], a[mf], b[nf]);
                    else           mma_fp16(acc[mf][nf], a[mf], b[nf]);
                }
            if (PREC == 0) {
                unsigned bl[4][2];
                #pragma unroll
                for (int nf = 0; nf < 4; nf++) {
                    const unsigned q = base + (unsigned)((wn + nf * 8 + g) * 8 + ks);
                    bl[nf][0] = Yl[q];  bl[nf][1] = Yl[q ^ 4];
                }
                #pragma unroll
                for (int mf = 0; mf < 4; mf++)
                    #pragma unroll
                    for (int nf = 0; nf < 4; nf++)
                        mma_bf16(acc[mf][nf], a[mf], bl[nf]);
                unsigned al[4][4];
                #pragma unroll
                for (int mf = 0; mf < 4; mf++) {
                    const unsigned p = base + (unsigned)((wm + mf * 16 + g) * 8 + ks);
                    al[mf][0] = Xl[p];      al[mf][1] = Xl[p + 64];
                    al[mf][2] = Xl[p ^ 4];  al[mf][3] = Xl[(p + 64) ^ 4];
                }
                #pragma unroll
                for (int mf = 0; mf < 4; mf++)
                    #pragma unroll
                    for (int nf = 0; nf < 4; nf++)
                        mma_bf16(acc[mf][nf], al[mf], b[nf]);
            }
        }
    };

    gload(0);
    sstore();
    __syncthreads();
    for (int kt = 0; kt < ktiles; kt++) {
        if (kt + 1 < ktiles) gload(kt + 1);
        compute();
        __syncthreads();
        if (kt + 1 < ktiles) { sstore(); __syncthreads(); }
    }

    // epilogue (C fragment layout identical to m16n8k8 path)
    #pragma unroll
    for (int mf = 0; mf < 4; mf++) {
        #pragma unroll
        for (int nf = 0; nf < 4; nf++) {
            const int row = bm + wm + mf * 16 + g;
            const int col = bn + wn + nf * 8 + t2;
            float v0 = acc[mf][nf][0], v1 = acc[mf][nf][1];
            float v2 = acc[mf][nf][2], v3 = acc[mf][nf][3];
            if (EPI == 0) {
                v0 *= scale; v1 *= scale; v2 *= scale; v3 *= scale;
            } else {
                const float bb0 = bias[col], bb1 = bias[col + 1];
                v0 += bb0; v1 += bb1; v2 += bb0; v3 += bb1;
                if (EPI == 2) {
                    v0 = v0 > 0.f ? v0 : expm1f(v0);
                    v1 = v1 > 0.f ? v1 : expm1f(v1);
                    v2 = v2 > 0.f ? v2 : expm1f(v2);
                    v3 = v3 > 0.f ? v3 : expm1f(v3);
                }
            }
            *reinterpret_cast<float2*>(C + (size_t)row * ldc + coff + col)       = make_float2(v0, v1);
            *reinterpret_cast<float2*>(C + (size_t)(row + 8) * ldc + coff + col) = make_float2(v2, v3);
        }
    }
}

// ------------------------------ softmax ------------------------------------
// read fp32 scores, write normalized fp16 (half2-packed u32 words)
__global__ void __launch_bounds__(256, 1)
softmax_rows(const float* __restrict__ S, unsigned* __restrict__ Sh)
{
    const int row = blockIdx.x;
    const float4* p = reinterpret_cast<const float4*>(S + (size_t)row * 8192);
    const int tid = threadIdx.x;

    float4 v[8];
    #pragma unroll
    for (int i = 0; i < 8; i++) v[i] = p[tid + 256 * i];

    float m = -3.402823e38f;
    #pragma unroll
    for (int i = 0; i < 8; i++)
        m = fmaxf(m, fmaxf(fmaxf(v[i].x, v[i].y), fmaxf(v[i].z, v[i].w)));

    __shared__ float red[8];
    #pragma unroll
    for (int o = 16; o; o >>= 1) m = fmaxf(m, __shfl_xor_sync(0xffffffffu, m, o));
    if ((tid & 31) == 0) red[tid >> 5] = m;
    __syncthreads();
    float mm = red[0];
    #pragma unroll
    for (int i = 1; i < 8; i++) mm = fmaxf(mm, red[i]);

    float s = 0.f;
    #pragma unroll
    for (int i = 0; i < 8; i++) {
        v[i].x = __expf(v[i].x - mm); s += v[i].x;
        v[i].y = __expf(v[i].y - mm); s += v[i].y;
        v[i].z = __expf(v[i].z - mm); s += v[i].z;
        v[i].w = __expf(v[i].w - mm); s += v[i].w;
    }
    #pragma unroll
    for (int o = 16; o; o >>= 1) s += __shfl_xor_sync(0xffffffffu, s, o);
    __syncthreads();
    if ((tid & 31) == 0) red[tid >> 5] = s;
    __syncthreads();
    float st = 0.f;
    #pragma unroll
    for (int i = 0; i < 8; i++) st += red[i];
    const float inv = 1.0f / st;

    unsigned* q = Sh + (size_t)row * 4096;
    #pragma unroll
    for (int i = 0; i < 8; i++) {
        uint2 w;
        w.x = packh2(v[i].x * inv, v[i].y * inv);
        w.y = packh2(v[i].z * inv, v[i].w * inv);
        *reinterpret_cast<uint2*>(q + (tid + 256 * i) * 2) = w;
    }
}

// ------------------------------ launcher -----------------------------------
extern "C" void kernel_launch(void* const* d_in, const int* in_sizes, int n_in,
                              void* d_out, int out_size)
{
    const float* za = (const float*)d_in[0];
    const float* zb = (const float*)d_in[1];
    const float* W1 = (const float*)d_in[2];
    const float* b1 = (const float*)d_in[3];
    const float* W2 = (const float*)d_in[4];
    const float* b2 = (const float*)d_in[5];
    const float* Wq = (const float*)d_in[6];
    const float* bq = (const float*)d_in[7];
    const float* Wk = (const float*)d_in[8];
    const float* bk = (const float*)d_in[9];
    const float* Wv = (const float*)d_in[10];
    const float* bv = (const float*)d_in[11];
    float* out = (float*)d_out;

    float *H, *P, *Q, *Kp, *V, *VT, *W1T, *W2T, *WqT, *WkT, *WvT, *S;
    unsigned* Sh;
    cudaGetSymbolAddress((void**)&H,   g_H);
    cudaGetSymbolAddress((void**)&P,   g_Pm);
    cudaGetSymbolAddress((void**)&Q,   g_Qm);
    cudaGetSymbolAddress((void**)&Kp,  g_Km);
    cudaGetSymbolAddress((void**)&V,   g_Vm);
    cudaGetSymbolAddress((void**)&VT,  g_VT);
    cudaGetSymbolAddress((void**)&W1T, g_W1T);
    cudaGetSymbolAddress((void**)&W2T, g_W2T);
    cudaGetSymbolAddress((void**)&WqT, g_WqT);
    cudaGetSymbolAddress((void**)&WkT, g_WkT);
    cudaGetSymbolAddress((void**)&WvT, g_WvT);
    cudaGetSymbolAddress((void**)&S,   g_S);
    cudaGetSymbolAddress((void**)&Sh,  g_Sh);

    const int smem_split  = 4 * SLAB * 4;   // 66048 B
    const int smem_single = 2 * SLAB * 4;   // 33024 B
    cudaFuncSetAttribute(gemm_mm<0,0>, cudaFuncAttributeMaxDynamicSharedMemorySize, smem_split);
    cudaFuncSetAttribute(gemm_mm<1,0>, cudaFuncAttributeMaxDynamicSharedMemorySize, smem_split);
    cudaFuncSetAttribute(gemm_mm<2,0>, cudaFuncAttributeMaxDynamicSharedMemorySize, smem_split);
    cudaFuncSetAttribute(gemm_mm<0,1>, cudaFuncAttributeMaxDynamicSharedMemorySize, smem_single);

    const dim3 blk(256);
    const dim3 tblk(32, 8);
    const float inv_scale = 1.0f / 16.0f;   // 1/sqrt(OUT/2)
    const size_t HALF = (size_t)8192 * 512;

    transpose_k<<<dim3(32, 32), tblk>>>(W1, W1T, 1024, 1024);
    transpose_k<<<dim3(16, 32), tblk>>>(W2, W2T, 1024, 512);
    transpose_k<<<dim3(16, 16), tblk>>>(Wq, WqT, 512, 512);
    transpose_k<<<dim3(16, 16), tblk>>>(Wk, WkT, 512, 512);
    transpose_k<<<dim3(16, 16), tblk>>>(Wv, WvT, 512, 512);

    // proj layer 1: H = ELU(X @ W1 + b1)
    gemm_mm<2,0><<<dim3(8, 64), blk, smem_split>>>(za, W1T, b1, H,                     8192, 1024, 1024, 1024, 0, 1.f);
    gemm_mm<2,0><<<dim3(8, 64), blk, smem_split>>>(zb, W1T, b1, H + (size_t)8192*1024, 8192, 1024, 1024, 1024, 0, 1.f);
    // proj layer 2: P = H @ W2 + b2
    gemm_mm<1,0><<<dim3(4, 128), blk, smem_split>>>(H, W2T, b2, P, 16384, 512, 1024, 512, 0, 1.f);
    // QKV
    gemm_mm<1,0><<<dim3(4, 128), blk, smem_split>>>(P, WqT, bq, Q,  16384, 512, 512, 512, 0, 1.f);
    gemm_mm<1,0><<<dim3(4, 128), blk, smem_split>>>(P, WkT, bk, Kp, 16384, 512, 512, 512, 0, 1.f);
    gemm_mm<1,0><<<dim3(4, 128), blk, smem_split>>>(P, WvT, bv, V,  16384, 512, 512, 512, 0, 1.f);
    // V transposed per half -> [512, 8192]
    transpose_k<<<dim3(16, 256), tblk>>>(V,        VT,        8192, 512);
    transpose_k<<<dim3(16, 256), tblk>>>(V + HALF, VT + HALF, 8192, 512);

    // direction A: out[:, 0:512] = softmax(Qa @ Kb^T / 16) @ Vb
    gemm_mm<0,0><<<dim3(64, 64), blk, smem_split>>>(Q, Kp + HALF, nullptr, S, 8192, 8192, 512, 8192, 0, inv_scale);
    softmax_rows<<<8192, blk>>>(S, Sh);
    gemm_mm<0,1><<<dim3(4, 64), blk, smem_single>>>(Sh, VT + HALF, nullptr, out, 8192, 512, 8192, 1024, 0, 1.f);

    // direction B: out[:, 512:1024] = softmax(Qb @ Ka^T / 16) @ Va
    gemm_mm<0,0><<<dim3(64, 64), blk, smem_split>>>(Q + HALF, Kp, nullptr, S, 8192, 8192, 512, 8192, 0, inv_scale);
    softmax_rows<<<8192, blk>>>(S, Sh);
    gemm_mm<0,1><<<dim3(4, 64), blk, smem_single>>>(Sh, VT, nullptr, out, 8192, 512, 8192, 1024, 512, 1.f);
}

// round 5
// speedup vs baseline: 1.8121x; 1.2967x over previous
#include <cuda_runtime.h>
#include <cuda_bf16.h>
#include <cuda_fp16.h>
#include <math.h>

// ---------------------------------------------------------------------------
// Contrast on legacy mma.sync m16n8k16 (baseline PTX; harness targets sm_103).
// All GEMM operands pre-split in GMEM: bf16 hi/lo pairs (split-3 GEMMs) or
// fp16 (AV GEMM). Staging is pure LDG.128->STS.128; epilogues emit split/fp16.
// ---------------------------------------------------------------------------

namespace {
constexpr int KBLK = 1032;        // u32 words per k16-block slab: 128*8 + 8 pad
constexpr int SLAB = 4 * KBLK;    // 4 k16-blocks per BK=64 tile
}

// ------------------------------ scratch (u32 words) -------------------------
__device__ unsigned g_Zh [8388608], g_Zl [8388608];   // split(za|zb) 16384x1024
__device__ unsigned g_Hh [8388608], g_Hl [8388608];   // H split     16384x1024
__device__ unsigned g_Ph [4194304], g_Pl [4194304];   // P split     16384x512
__device__ unsigned g_Qh [4194304], g_Ql [4194304];
__device__ unsigned g_Kh [4194304], g_Kl [4194304];
__device__ unsigned g_Vh [4194304];                   // V fp16      16384x512
__device__ unsigned g_VT [4194304];                   // V^T fp16, per half [512,8192]
__device__ unsigned g_W1h[524288],  g_W1l[524288];    // W1^T split  1024x1024
__device__ unsigned g_W2h[262144],  g_W2l[262144];    // W2^T split  512x1024
__device__ unsigned g_Wqh[131072],  g_Wql[131072];    // Wq^T split  512x512
__device__ unsigned g_Wkh[131072],  g_Wkl[131072];
__device__ unsigned g_Wvh[131072],  g_Wvl[131072];
__device__ float    g_S  [67108864];                  // fp32 scores 8192x8192
__device__ unsigned g_Sh [33554432];                  // fp16 softmaxed scores

// ------------------------------ helpers ------------------------------------
__device__ __forceinline__ void mma_bf16(float* c, const unsigned* a, const unsigned* b) {
    asm volatile(
        "mma.sync.aligned.m16n8k16.row.col.f32.bf16.bf16.f32 "
        "{%0,%1,%2,%3}, {%4,%5,%6,%7}, {%8,%9}, {%0,%1,%2,%3};"
        : "+f"(c[0]), "+f"(c[1]), "+f"(c[2]), "+f"(c[3])
        : "r"(a[0]), "r"(a[1]), "r"(a[2]), "r"(a[3]), "r"(b[0]), "r"(b[1]));
}

__device__ __forceinline__ void mma_fp16(float* c, const unsigned* a, const unsigned* b) {
    asm volatile(
        "mma.sync.aligned.m16n8k16.row.col.f32.f16.f16.f32 "
        "{%0,%1,%2,%3}, {%4,%5,%6,%7}, {%8,%9}, {%0,%1,%2,%3};"
        : "+f"(c[0]), "+f"(c[1]), "+f"(c[2]), "+f"(c[3])
        : "r"(a[0]), "r"(a[1]), "r"(a[2]), "r"(a[3]), "r"(b[0]), "r"(b[1]));
}

__device__ __forceinline__ void split2(float x, float y, unsigned& hi, unsigned& lo) {
    __nv_bfloat16 hx = __float2bfloat16(x);
    __nv_bfloat16 hy = __float2bfloat16(y);
    __nv_bfloat16 lx = __float2bfloat16(x - __bfloat162float(hx));
    __nv_bfloat16 ly = __float2bfloat16(y - __bfloat162float(hy));
    hi = ((unsigned)__bfloat16_as_ushort(hy) << 16) | (unsigned)__bfloat16_as_ushort(hx);
    lo = ((unsigned)__bfloat16_as_ushort(ly) << 16) | (unsigned)__bfloat16_as_ushort(lx);
}

__device__ __forceinline__ unsigned packh2(float x, float y) {
    __half2 h = __floats2half2_rn(x, y);
    return *reinterpret_cast<unsigned*>(&h);
}

// --------------------------- input split -----------------------------------
// (za|zb) f32 -> Zh/Zl bf16 split; 4 floats per thread
__global__ void __launch_bounds__(256, 8)
split_in(const float* __restrict__ za, const float* __restrict__ zb,
         unsigned* __restrict__ Zh, unsigned* __restrict__ Zl)
{
    const size_t t = (size_t)blockIdx.x * 256 + threadIdx.x;
    const size_t f = t * 4;
    const float4 v = (f < (size_t)8388608)
        ? *reinterpret_cast<const float4*>(za + f)
        : *reinterpret_cast<const float4*>(zb + (f - 8388608));
    uint2 h, l;
    split2(v.x, v.y, h.x, l.x);
    split2(v.z, v.w, h.y, l.y);
    *reinterpret_cast<uint2*>(Zh + t * 2) = h;
    *reinterpret_cast<uint2*>(Zl + t * 2) = l;
}

// --------------------------- weight transpose + split -----------------------
// dst[C,R] = split(src[R,C]^T); dh/dl viewed as ushort[C][R]
__global__ void __launch_bounds__(256, 4)
transpose_split(const float* __restrict__ src, unsigned* __restrict__ dh,
                unsigned* __restrict__ dl, int R, int C)
{
    __shared__ float t[32][33];
    const int bx = blockIdx.x * 32;
    const int by = blockIdx.y * 32;
    const int x  = bx + threadIdx.x;
    #pragma unroll
    for (int i = threadIdx.y; i < 32; i += 8)
        t[i][threadIdx.x] = src[(size_t)(by + i) * C + x];
    __syncthreads();
    const int xo = by + threadIdx.x;
    unsigned short* ph = reinterpret_cast<unsigned short*>(dh);
    unsigned short* pl = reinterpret_cast<unsigned short*>(dl);
    #pragma unroll
    for (int i = threadIdx.y; i < 32; i += 8) {
        const float v = t[threadIdx.x][i];
        const __nv_bfloat16 h = __float2bfloat16(v);
        const __nv_bfloat16 l = __float2bfloat16(v - __bfloat162float(h));
        ph[(size_t)(bx + i) * R + xo] = __bfloat16_as_ushort(h);
        pl[(size_t)(bx + i) * R + xo] = __bfloat16_as_ushort(l);
    }
}

// --------------------------- fp16 transpose --------------------------------
// dst u16[C,R] = src u16[R,C]^T
__global__ void __launch_bounds__(256, 4)
transpose_h(const unsigned* __restrict__ srcw, unsigned* __restrict__ dstw, int R, int C)
{
    __shared__ unsigned short t[32][34];
    const unsigned short* src = reinterpret_cast<const unsigned short*>(srcw);
    unsigned short* dst = reinterpret_cast<unsigned short*>(dstw);
    const int bx = blockIdx.x * 32;
    const int by = blockIdx.y * 32;
    const int x  = bx + threadIdx.x;
    #pragma unroll
    for (int i = threadIdx.y; i < 32; i += 8)
        t[i][threadIdx.x] = src[(size_t)(by + i) * C + x];
    __syncthreads();
    const int xo = by + threadIdx.x;
    #pragma unroll
    for (int i = threadIdx.y; i < 32; i += 8)
        dst[(size_t)(bx + i) * R + xo] = t[threadIdx.x][i];
}

// ------------------------------ GEMM ---------------------------------------
// C = epi(A[M,K] @ B[N,K]^T), operands pre-packed 16-bit (u32 pitch K/2).
// PREC 0: bf16 split-3 (Ah/Al, Bh/Bl).  PREC 1: fp16 single (Ah, Bh).
// EPI 0: v*=scale ; EPI 1: v+=bias ; EPI 2: elu(v+bias)
// OFMT 0: f32 Cf (ldc floats, +coff) ; OFMT 1: split bf16 Ch/Cl (ldc words)
// OFMT 2: fp16 Ch (ldc words)
template <int EPI, int PREC, int OFMT>
__global__ void __launch_bounds__(256, 1)
gemm_mm(const unsigned* __restrict__ Ah, const unsigned* __restrict__ Al,
        const unsigned* __restrict__ Bh, const unsigned* __restrict__ Bl,
        const float* __restrict__ bias,
        float* __restrict__ Cf, unsigned* __restrict__ Ch, unsigned* __restrict__ Cl,
        int M, int N, int K, int ldc, int coff, float scale)
{
    extern __shared__ unsigned sm[];
    unsigned* Xh = sm;
    unsigned* Xl = Xh + SLAB;
    unsigned* Yh = sm + (PREC == 0 ? 2 : 1) * SLAB;
    unsigned* Yl = Yh + SLAB;

    const int tid  = threadIdx.x;
    const int bm   = blockIdx.y * 128;
    const int bn   = blockIdx.x * 128;
    const int warp = tid >> 5;
    const int lane = tid & 31;
    const int wm   = (warp >> 2) * 64;
    const int wn   = (warp & 3) * 32;
    const int g    = lane >> 2;
    const int tk   = lane & 3;
    const int t2   = tk * 2;
    const int swz  = ((g >> 2) & 1) * 4;
    const int ks   = tk ^ swz;

    const int srow  = tid >> 3;              // 0..31 (+32*i)
    const int scol8 = (tid & 7) * 8;         // k elem offset 0..56
    const int sblk  = scol8 >> 4;
    const int sw0   = ((scol8 & 15) >> 1) ^ (((srow >> 2) & 1) * 4);

    const int kw = K >> 1;                   // word pitch

    float acc[4][4][4];
    #pragma unroll
    for (int i = 0; i < 4; i++)
        #pragma unroll
        for (int j = 0; j < 4; j++)
            #pragma unroll
            for (int e = 0; e < 4; e++) acc[i][j][e] = 0.f;

    uint4 ha[4], la[4], hb[4], lb[4];
    const int ktiles = K / 64;

    auto gload = [&](int kt) {
        const int w0 = kt * 32 + (scol8 >> 1);
        #pragma unroll
        for (int i = 0; i < 4; i++) {
            const size_t ro = (size_t)(bm + srow + 32 * i) * kw + w0;
            ha[i] = *reinterpret_cast<const uint4*>(Ah + ro);
            if (PREC == 0) la[i] = *reinterpret_cast<const uint4*>(Al + ro);
        }
        #pragma unroll
        for (int i = 0; i < 4; i++) {
            const size_t ro = (size_t)(bn + srow + 32 * i) * kw + w0;
            hb[i] = *reinterpret_cast<const uint4*>(Bh + ro);
            if (PREC == 0) lb[i] = *reinterpret_cast<const uint4*>(Bl + ro);
        }
    };

    auto sstore = [&]() {
        #pragma unroll
        for (int i = 0; i < 4; i++) {
            const unsigned sidx = (unsigned)(sblk * KBLK + (srow + 32 * i) * 8 + sw0);
            *reinterpret_cast<uint4*>(&Xh[sidx]) = ha[i];
            *reinterpret_cast<uint4*>(&Yh[sidx]) = hb[i];
            if (PREC == 0) {
                *reinterpret_cast<uint4*>(&Xl[sidx]) = la[i];
                *reinterpret_cast<uint4*>(&Yl[sidx]) = lb[i];
            }
        }
    };

    auto compute = [&]() {
        #pragma unroll
        for (int blk = 0; blk < 4; blk++) {
            const unsigned base = (unsigned)(blk * KBLK);
            unsigned a[4][4], b[4][2];
            #pragma unroll
            for (int mf = 0; mf < 4; mf++) {
                const unsigned p = base + (unsigned)((wm + mf * 16 + g) * 8 + ks);
                a[mf][0] = Xh[p];       a[mf][1] = Xh[p + 64];
                a[mf][2] = Xh[p ^ 4];   a[mf][3] = Xh[(p + 64) ^ 4];
            }
            #pragma unroll
            for (int nf = 0; nf < 4; nf++) {
                const unsigned q = base + (unsigned)((wn + nf * 8 + g) * 8 + ks);
                b[nf][0] = Yh[q];       b[nf][1] = Yh[q ^ 4];
            }
            #pragma unroll
            for (int mf = 0; mf < 4; mf++)
                #pragma unroll
                for (int nf = 0; nf < 4; nf++) {
                    if (PREC == 0) mma_bf16(acc[mf][nf], a[mf], b[nf]);
                    else           mma_fp16(acc[mf][nf], a[mf], b[nf]);
                }
            if (PREC == 0) {
                unsigned bl2[4][2];
                #pragma unroll
                for (int nf = 0; nf < 4; nf++) {
                    const unsigned q = base + (unsigned)((wn + nf * 8 + g) * 8 + ks);
                    bl2[nf][0] = Yl[q];  bl2[nf][1] = Yl[q ^ 4];
                }
                #pragma unroll
                for (int mf = 0; mf < 4; mf++)
                    #pragma unroll
                    for (int nf = 0; nf < 4; nf++)
                        mma_bf16(acc[mf][nf], a[mf], bl2[nf]);
                unsigned al2[4][4];
                #pragma unroll
                for (int mf = 0; mf < 4; mf++) {
                    const unsigned p = base + (unsigned)((wm + mf * 16 + g) * 8 + ks);
                    al2[mf][0] = Xl[p];      al2[mf][1] = Xl[p + 64];
                    al2[mf][2] = Xl[p ^ 4];  al2[mf][3] = Xl[(p + 64) ^ 4];
                }
                #pragma unroll
                for (int mf = 0; mf < 4; mf++)
                    #pragma unroll
                    for (int nf = 0; nf < 4; nf++)
                        mma_bf16(acc[mf][nf], al2[mf], b[nf]);
            }
        }
    };

    gload(0);
    sstore();
    __syncthreads();
    for (int kt = 0; kt < ktiles; kt++) {
        if (kt + 1 < ktiles) gload(kt + 1);
        compute();
        __syncthreads();
        if (kt + 1 < ktiles) { sstore(); __syncthreads(); }
    }

    // epilogue
    #pragma unroll
    for (int mf = 0; mf < 4; mf++) {
        #pragma unroll
        for (int nf = 0; nf < 4; nf++) {
            const int row = bm + wm + mf * 16 + g;
            const int col = bn + wn + nf * 8 + t2;
            float v0 = acc[mf][nf][0], v1 = acc[mf][nf][1];
            float v2 = acc[mf][nf][2], v3 = acc[mf][nf][3];
            if (EPI == 0) {
                v0 *= scale; v1 *= scale; v2 *= scale; v3 *= scale;
            } else {
                const float bb0 = bias[col], bb1 = bias[col + 1];
                v0 += bb0; v1 += bb1; v2 += bb0; v3 += bb1;
                if (EPI == 2) {
                    v0 = v0 > 0.f ? v0 : expm1f(v0);
                    v1 = v1 > 0.f ? v1 : expm1f(v1);
                    v2 = v2 > 0.f ? v2 : expm1f(v2);
                    v3 = v3 > 0.f ? v3 : expm1f(v3);
                }
            }
            if (OFMT == 0) {
                *reinterpret_cast<float2*>(Cf + (size_t)row * ldc + coff + col)       = make_float2(v0, v1);
                *reinterpret_cast<float2*>(Cf + (size_t)(row + 8) * ldc + coff + col) = make_float2(v2, v3);
            } else if (OFMT == 1) {
                unsigned h, l;
                split2(v0, v1, h, l);
                Ch[(size_t)row * ldc + (col >> 1)] = h;
                Cl[(size_t)row * ldc + (col >> 1)] = l;
                split2(v2, v3, h, l);
                Ch[(size_t)(row + 8) * ldc + (col >> 1)] = h;
                Cl[(size_t)(row + 8) * ldc + (col >> 1)] = l;
            } else {
                Ch[(size_t)row * ldc + (col >> 1)]       = packh2(v0, v1);
                Ch[(size_t)(row + 8) * ldc + (col >> 1)] = packh2(v2, v3);
            }
        }
    }
}

// ------------------------------ softmax ------------------------------------
__global__ void __launch_bounds__(256, 1)
softmax_rows(const float* __restrict__ S, unsigned* __restrict__ Sh)
{
    const int row = blockIdx.x;
    const float4* p = reinterpret_cast<const float4*>(S + (size_t)row * 8192);
    const int tid = threadIdx.x;

    float4 v[8];
    #pragma unroll
    for (int i = 0; i < 8; i++) v[i] = p[tid + 256 * i];

    float m = -3.402823e38f;
    #pragma unroll
    for (int i = 0; i < 8; i++)
        m = fmaxf(m, fmaxf(fmaxf(v[i].x, v[i].y), fmaxf(v[i].z, v[i].w)));

    __shared__ float red[8];
    #pragma unroll
    for (int o = 16; o; o >>= 1) m = fmaxf(m, __shfl_xor_sync(0xffffffffu, m, o));
    if ((tid & 31) == 0) red[tid >> 5] = m;
    __syncthreads();
    float mm = red[0];
    #pragma unroll
    for (int i = 1; i < 8; i++) mm = fmaxf(mm, red[i]);

    float s = 0.f;
    #pragma unroll
    for (int i = 0; i < 8; i++) {
        v[i].x = __expf(v[i].x - mm); s += v[i].x;
        v[i].y = __expf(v[i].y - mm); s += v[i].y;
        v[i].z = __expf(v[i].z - mm); s += v[i].z;
        v[i].w = __expf(v[i].w - mm); s += v[i].w;
    }
    #pragma unroll
    for (int o = 16; o; o >>= 1) s += __shfl_xor_sync(0xffffffffu, s, o);
    __syncthreads();
    if ((tid & 31) == 0) red[tid >> 5] = s;
    __syncthreads();
    float st = 0.f;
    #pragma unroll
    for (int i = 0; i < 8; i++) st += red[i];
    const float inv = 1.0f / st;

    unsigned* q = Sh + (size_t)row * 4096;
    #pragma unroll
    for (int i = 0; i < 8; i++) {
        uint2 w;
        w.x = packh2(v[i].x * inv, v[i].y * inv);
        w.y = packh2(v[i].z * inv, v[i].w * inv);
        *reinterpret_cast<uint2*>(q + (tid + 256 * i) * 2) = w;
    }
}

// ------------------------------ launcher -----------------------------------
extern "C" void kernel_launch(void* const* d_in, const int* in_sizes, int n_in,
                              void* d_out, int out_size)
{
    const float* za = (const float*)d_in[0];
    const float* zb = (const float*)d_in[1];
    const float* W1 = (const float*)d_in[2];
    const float* b1 = (const float*)d_in[3];
    const float* W2 = (const float*)d_in[4];
    const float* b2 = (const float*)d_in[5];
    const float* Wq = (const float*)d_in[6];
    const float* bq = (const float*)d_in[7];
    const float* Wk = (const float*)d_in[8];
    const float* bk = (const float*)d_in[9];
    const float* Wv = (const float*)d_in[10];
    const float* bv = (const float*)d_in[11];
    float* out = (float*)d_out;

    unsigned *Zh, *Zl, *Hh, *Hl, *Ph, *Pl, *Qh, *Ql, *Kh, *Kl, *Vh, *VT;
    unsigned *W1h, *W1l, *W2h, *W2l, *Wqh, *Wql, *Wkh, *Wkl, *Wvh, *Wvl, *Sh;
    float *S;
    cudaGetSymbolAddress((void**)&Zh,  g_Zh);  cudaGetSymbolAddress((void**)&Zl,  g_Zl);
    cudaGetSymbolAddress((void**)&Hh,  g_Hh);  cudaGetSymbolAddress((void**)&Hl,  g_Hl);
    cudaGetSymbolAddress((void**)&Ph,  g_Ph);  cudaGetSymbolAddress((void**)&Pl,  g_Pl);
    cudaGetSymbolAddress((void**)&Qh,  g_Qh);  cudaGetSymbolAddress((void**)&Ql,  g_Ql);
    cudaGetSymbolAddress((void**)&Kh,  g_Kh);  cudaGetSymbolAddress((void**)&Kl,  g_Kl);
    cudaGetSymbolAddress((void**)&Vh,  g_Vh);  cudaGetSymbolAddress((void**)&VT,  g_VT);
    cudaGetSymbolAddress((void**)&W1h, g_W1h); cudaGetSymbolAddress((void**)&W1l, g_W1l);
    cudaGetSymbolAddress((void**)&W2h, g_W2h); cudaGetSymbolAddress((void**)&W2l, g_W2l);
    cudaGetSymbolAddress((void**)&Wqh, g_Wqh); cudaGetSymbolAddress((void**)&Wql, g_Wql);
    cudaGetSymbolAddress((void**)&Wkh, g_Wkh); cudaGetSymbolAddress((void**)&Wkl, g_Wkl);
    cudaGetSymbolAddress((void**)&Wvh, g_Wvh); cudaGetSymbolAddress((void**)&Wvl, g_Wvl);
    cudaGetSymbolAddress((void**)&S,   g_S);   cudaGetSymbolAddress((void**)&Sh,  g_Sh);

    const int smem_split  = 4 * SLAB * 4;   // 66048 B
    const int smem_single = 2 * SLAB * 4;   // 33024 B
    cudaFuncSetAttribute(gemm_mm<0,0,0>, cudaFuncAttributeMaxDynamicSharedMemorySize, smem_split);
    cudaFuncSetAttribute(gemm_mm<1,0,1>, cudaFuncAttributeMaxDynamicSharedMemorySize, smem_split);
    cudaFuncSetAttribute(gemm_mm<2,0,1>, cudaFuncAttributeMaxDynamicSharedMemorySize, smem_split);
    cudaFuncSetAttribute(gemm_mm<1,0,2>, cudaFuncAttributeMaxDynamicSharedMemorySize, smem_split);
    cudaFuncSetAttribute(gemm_mm<0,1,0>, cudaFuncAttributeMaxDynamicSharedMemorySize, smem_single);

    const dim3 blk(256);
    const dim3 tblk(32, 8);
    const float inv_scale = 1.0f / 16.0f;   // 1/sqrt(OUT/2)
    const size_t HALFW = (size_t)8192 * 256;   // word offset: half of Q/K/V split arrays
    const size_t HVTW  = (size_t)512 * 4096;   // word offset: half of VT

    // input split + weight transposes
    split_in<<<16384, blk>>>(za, zb, Zh, Zl);
    transpose_split<<<dim3(32, 32), tblk>>>(W1, W1h, W1l, 1024, 1024);
    transpose_split<<<dim3(16, 32), tblk>>>(W2, W2h, W2l, 1024, 512);
    transpose_split<<<dim3(16, 16), tblk>>>(Wq, Wqh, Wql, 512, 512);
    transpose_split<<<dim3(16, 16), tblk>>>(Wk, Wkh, Wkl, 512, 512);
    transpose_split<<<dim3(16, 16), tblk>>>(Wv, Wvh, Wvl, 512, 512);

    // proj layer 1: H = ELU(Z @ W1^T + b1)   [16384 x 1024]
    gemm_mm<2,0,1><<<dim3(8, 128), blk, smem_split>>>(
        Zh, Zl, W1h, W1l, b1, nullptr, Hh, Hl, 16384, 1024, 1024, 512, 0, 1.f);
    // proj layer 2: P = H @ W2^T + b2        [16384 x 512]
    gemm_mm<1,0,1><<<dim3(4, 128), blk, smem_split>>>(
        Hh, Hl, W2h, W2l, b2, nullptr, Ph, Pl, 16384, 512, 1024, 256, 0, 1.f);
    // QKV
    gemm_mm<1,0,1><<<dim3(4, 128), blk, smem_split>>>(
        Ph, Pl, Wqh, Wql, bq, nullptr, Qh, Ql, 16384, 512, 512, 256, 0, 1.f);
    gemm_mm<1,0,1><<<dim3(4, 128), blk, smem_split>>>(
        Ph, Pl, Wkh, Wkl, bk, nullptr, Kh, Kl, 16384, 512, 512, 256, 0, 1.f);
    gemm_mm<1,0,2><<<dim3(4, 128), blk, smem_split>>>(
        Ph, Pl, Wvh, Wvl, bv, nullptr, Vh, nullptr, 16384, 512, 512, 256, 0, 1.f);
    // V^T per half (fp16): [8192,512] -> [512,8192]
    transpose_h<<<dim3(16, 256), tblk>>>(Vh,         VT,        8192, 512);
    transpose_h<<<dim3(16, 256), tblk>>>(Vh + HALFW, VT + HVTW, 8192, 512);

    // direction A: out[:, 0:512] = softmax(Qa @ Kb^T / 16) @ Vb
    gemm_mm<0,0,0><<<dim3(64, 64), blk, smem_split>>>(
        Qh, Ql, Kh + HALFW, Kl + HALFW, nullptr, S, nullptr, nullptr,
        8192, 8192, 512, 8192, 0, inv_scale);
    softmax_rows<<<8192, blk>>>(S, Sh);
    gemm_mm<0,1,0><<<dim3(4, 64), blk, smem_single>>>(
        Sh, nullptr, VT + HVTW, nullptr, nullptr, out, nullptr, nullptr,
        8192, 512, 8192, 1024, 0, 1.f);

    // direction B: out[:, 512:1024] = softmax(Qb @ Ka^T / 16) @ Va
    gemm_mm<0,0,0><<<dim3(64, 64), blk, smem_split>>>(
        Qh + HALFW, Ql + HALFW, Kh, Kl, nullptr, S, nullptr, nullptr,
        8192, 8192, 512, 8192, 0, inv_scale);
    softmax_rows<<<8192, blk>>>(S, Sh);
    gemm_mm<0,1,0><<<dim3(4, 64), blk, smem_single>>>(
        Sh, nullptr, VT, nullptr, nullptr, out, nullptr, nullptr,
        8192, 512, 8192, 1024, 512, 1.f);
}